// round 13
// baseline (speedup 1.0000x reference)
#include <cuda_runtime.h>
#include <cuda_fp16.h>
#include <cstdint>
#include <cstddef>

// ---------------- problem constants ----------------
#define V_SIZE 1024
#define H_SIZE 2048
#define F_SIZE 3072
#define T_STEPS 64
#define REC_F 0.8f

// ---------------- GEMM tiling (mixed-width, dual-CTA-per-SM) ----------------
#define BM 128
#define BK 64
#define KCHUNKS (F_SIZE / BK)   // 48
#define NTHREADS 128            // 4 warps: 2(M) x 2(N)
#define NSTAGES 2

// SMEM per stage: A(16K) Bh(<=11264) Bl(<=11264)
#define OFF_A  0
#define OFF_BH 16384
#define OFF_BL 27648
#define STAGE_BYTES 38912
// layout: [align slack 1K][hdr 1K: mbarriers][2 stages] ~78KB -> 2 CTAs/SM
#define SMEM_BYTES (1024 + 1024 + NSTAGES * STAGE_BYTES)

template <int N> struct IC { static constexpr int value = N; };

// ---------------- device scratch ----------------
__device__ __half g_Wh[(size_t)F_SIZE * F_SIZE];
__device__ __half g_Wl[(size_t)F_SIZE * F_SIZE];
__device__ __half g_R[2][(size_t)V_SIZE * F_SIZE];

__device__ __forceinline__ uint32_t swz(uint32_t o) { return o ^ ((o >> 3) & 0x70u); }

#define LDM4(R_, A_)                                                              \
  asm volatile("ldmatrix.sync.aligned.m8n8.x4.shared.b16 {%0,%1,%2,%3}, [%4];"    \
               : "=r"((R_)[0]), "=r"((R_)[1]), "=r"((R_)[2]), "=r"((R_)[3])       \
               : "r"(A_))

#define LDM2(R_, A_)                                                              \
  asm volatile("ldmatrix.sync.aligned.m8n8.x2.shared.b16 {%0,%1}, [%2];"          \
               : "=r"((R_)[0]), "=r"((R_)[1]) : "r"(A_))

#define MMA16816(C_, A_, B0_, B1_)                                                \
  asm volatile("mma.sync.aligned.m16n8k16.row.col.f32.f16.f16.f32 "               \
               "{%0,%1,%2,%3},{%4,%5,%6,%7},{%8,%9},{%0,%1,%2,%3};"               \
               : "+f"((C_)[0]), "+f"((C_)[1]), "+f"((C_)[2]), "+f"((C_)[3])       \
               : "r"((A_)[0]), "r"((A_)[1]), "r"((A_)[2]), "r"((A_)[3]),          \
                 "r"(B0_), "r"(B1_))

#define CP16(SO_, G_)                                                             \
  asm volatile("cp.async.cg.shared.global [%0], [%1], 16;" :: "r"(SO_), "l"(G_))

#define CP_ASYNC_MBAR_ARRIVE_NOINC(mbar)                                          \
  asm volatile("cp.async.mbarrier.arrive.noinc.shared.b64 [%0];"                  \
               :: "r"((uint32_t)(mbar)) : "memory")

#define MBARRIER_INIT(mbar, count)                                                \
  asm volatile("mbarrier.init.shared.b64 [%0], %1;"                               \
               :: "r"((uint32_t)(mbar)), "r"((uint32_t)(count)) : "memory")
#define MBARRIER_ARRIVE(mbar)                                                     \
  asm volatile("mbarrier.arrive.shared.b64 _, [%0];"                              \
               :: "r"((uint32_t)(mbar)) : "memory")

__device__ __forceinline__ void mbar_wait_parity(uint32_t mbar, uint32_t parity) {
  uint32_t done;
  asm volatile("{\n\t.reg .pred p;\n\t"
               "mbarrier.try_wait.parity.acquire.cta.shared::cta.b64 p, [%1], %2;\n\t"
               "selp.b32 %0, 1, 0, p;\n\t}"
               : "=r"(done) : "r"(mbar), "r"(parity) : "memory");
  if (!done) {
    asm volatile("{\n\t.reg .pred P1;\n\t"
                 "WAIT_LOOP_%=:\n\t"
                 "mbarrier.try_wait.parity.acquire.cta.shared::cta.b64 P1, [%0], %1, 0x989680;\n\t"
                 "@P1 bra.uni WAIT_DONE_%=;\n\t"
                 "bra.uni WAIT_LOOP_%=;\n\t"
                 "WAIT_DONE_%=:\n\t}"
                 :: "r"(mbar), "r"(parity) : "memory");
  }
}

#define HALF2_POW2_M6 0x24002400u
__device__ __forceinline__ uint32_t hmul2_scale(uint32_t a) {
  uint32_t r;
  asm volatile("mul.f16x2 %0, %1, %2;" : "=r"(r) : "r"(a), "r"(HALF2_POW2_M6));
  return r;
}

__device__ __forceinline__ float fast_tanh(float x) {
  float e = __expf(2.f * x);
  return 1.f - __fdividef(2.f, e + 1.f);
}

// -------- W split: fp32 -> fp16 hi + fp16 lo (lo pre-scaled by 2^6) --------
__global__ void split_w_kernel(const float* __restrict__ W) {
  const int n = F_SIZE * F_SIZE;
  for (int i = blockIdx.x * blockDim.x + threadIdx.x; i < n;
       i += gridDim.x * blockDim.x) {
    float w = W[i];
    __half h = __float2half(w);
    g_Wh[i] = h;
    g_Wl[i] = __float2half((w - __half2float(h)) * 64.f);
  }
}

// -------- step 0: R_0 = 0, epilogue-only --------
__global__ void step0_kernel(const float* __restrict__ X,
                             const float* __restrict__ b,
                             const float* __restrict__ lam) {
  const int n = V_SIZE * F_SIZE;
  for (int i = blockIdx.x * blockDim.x + threadIdx.x; i < n;
       i += gridDim.x * blockDim.x) {
    int c = i % F_SIZE;
    float l = lam[i];
    float u = l * b[c];
    if (c < V_SIZE) u += (1.f - l) * X[c];  // x_0
    g_R[1][i] = __float2half(tanhf(u));
  }
}

// -------- steps 1..62: C = R @ W^T (fp16 2-pass) + fused epilogue --------
// Mixed-width tiles: nW wide (88-col) + nN narrow (80-col) tiles per M-band.
// Wide tiles occupy bids [0, 8*nW) so the SM pair {bid, bid+P} is always
// (wide, narrow) or (narrow, narrow) under modular placement.
__global__ void __launch_bounds__(NTHREADS, 2)
gemm_step_kernel(int t, const float* __restrict__ X, const float* __restrict__ b,
                 int nW, int nN) {
  extern __shared__ unsigned char smem_raw[];
  uint32_t sbase = (uint32_t)__cvta_generic_to_shared(smem_raw);
  sbase = (sbase + 1023u) & ~1023u;
  const uint32_t hdr = sbase;        // full[s]=hdr+s*8, empty[s]=hdr+64+s*8
  const uint32_t tiles = sbase + 1024;

  // ---- bid -> (m0, n0, width) ----
  const int bid = blockIdx.x;
  const int wideTotal = nW * 8;
  bool wide;
  int band, n0;
  if (bid < wideTotal) {
    wide = true;
    band = bid / nW;
    n0 = (bid % nW) * 88;
  } else {
    int idx = bid - wideTotal;
    wide = false;
    band = idx / nN;
    n0 = nW * 88 + (idx % nN) * 80;
  }
  const int m0 = band * BM;
  const int width = wide ? 88 : 80;
  const int bItems = width * 8;           // 16B chunks per B tile
  const int totItems = 1024 + 2 * bItems; // A + Bh + Bl

  const __half* __restrict__ A = g_R[t & 1];
  __half* __restrict__ O = g_R[(t + 1) & 1];
  const float* __restrict__ Xr = X + (size_t)t * V_SIZE;

  const int tid = threadIdx.x;
  const int lane = tid & 31;
  const int wid = tid >> 5;
  const int wm = (wid >> 1) * 64;                       // 0 / 64
  const int wn = (wid & 1) ? (wide ? 48 : 40) : 0;      // N half base
  const int nfc = (wid & 1) ? 5 : (wide ? 6 : 5);       // frags this warp

  const __half* __restrict__ srcA  = A + (size_t)m0 * F_SIZE;
  const __half* __restrict__ srcBh = g_Wh + (size_t)n0 * F_SIZE;
  const __half* __restrict__ srcBl = g_Wl + (size_t)n0 * F_SIZE;

  if (tid == 0) {
#pragma unroll
    for (int s = 0; s < NSTAGES; ++s) {
      MBARRIER_INIT(hdr + s * 8, NTHREADS);       // full[s]
      MBARRIER_INIT(hdr + 64 + s * 8, NTHREADS);  // empty[s]
    }
  }
  __syncthreads();

  float acc[4][6][4];
#pragma unroll
  for (int i = 0; i < 4; ++i)
#pragma unroll
    for (int j = 0; j < 6; ++j)
#pragma unroll
      for (int k = 0; k < 4; ++k) acc[i][j][k] = 0.f;

  // --- async tile loader ---
  auto load_chunk = [&](int stage, int kc) {
    const uint32_t sb = tiles + (uint32_t)stage * STAGE_BYTES;
    const int koff = kc * BK;
    for (int i = tid; i < totItems; i += NTHREADS) {
      const __half* gb;
      uint32_t stile;
      int j;
      if (i < 1024) {                // A tile (128 rows x 8 chunks)
        j = i; gb = srcA; stile = OFF_A;
      } else {
        j = i - 1024;
        if (j < bItems) { gb = srcBh; stile = OFF_BH; }
        else            { j -= bItems; gb = srcBl; stile = OFF_BL; }
      }
      int r = j >> 3, c = j & 7;
      const void* g = gb + (size_t)r * F_SIZE + koff + c * 8;
      uint32_t so = sb + stile + swz((uint32_t)(r * 128 + c * 16));
      CP16(so, g);
    }
    CP_ASYNC_MBAR_ARRIVE_NOINC(hdr + stage * 8);  // full[stage]
  };

  // --- warp compute, NF fragments in N (templated 5 / 6) ---
  auto computeT = [&](auto nfc_, int stage) {
    constexpr int NF = decltype(nfc_)::value;
    const uint32_t sb = tiles + (uint32_t)stage * STAGE_BYTES;
    const uint32_t aT = sb + OFF_A;
    const uint32_t bH = sb + OFF_BH;
    const uint32_t bL = sb + OFF_BL;
#pragma unroll
    for (int ks = 0; ks < 4; ++ks) {
      uint32_t ah[4][4], as[4][4], bh[3][4], bl[3][4];
#pragma unroll
      for (int mf = 0; mf < 4; ++mf) {
        uint32_t off = swz((uint32_t)((wm + mf * 16 + (lane & 15)) * 128 +
                                      (ks * 16 + ((lane >> 4) << 3)) * 2));
        LDM4(ah[mf], aT + off);
#pragma unroll
        for (int q = 0; q < 4; ++q) as[mf][q] = hmul2_scale(ah[mf][q]);
      }
#pragma unroll
      for (int nf2 = 0; nf2 < NF / 2; ++nf2) {
        uint32_t off = swz((uint32_t)(
            (wn + nf2 * 16 + (lane & 7) + (((lane >> 4) & 1) << 3)) * 128 +
            (ks * 16 + ((lane >> 3) & 1) * 8) * 2));
        LDM4(bh[nf2], bH + off);
        LDM4(bl[nf2], bL + off);
      }
      if (NF & 1) {  // odd trailing 8-col fragment via x2
        uint32_t off = swz((uint32_t)(
            (wn + (NF / 2) * 16 + (lane & 7)) * 128 +
            (ks * 16 + ((lane >> 3) & 1) * 8) * 2));
        LDM2(bh[NF / 2], bH + off);
        LDM2(bl[NF / 2], bL + off);
      }
      if (ks == 3) MBARRIER_ARRIVE(hdr + 64 + stage * 8);  // empty[stage]
#pragma unroll
      for (int mf = 0; mf < 4; ++mf)
#pragma unroll
        for (int nf = 0; nf < NF; ++nf) {
          float* c = acc[mf][nf];
          uint32_t b0h = bh[nf >> 1][(nf & 1) * 2];
          uint32_t b1h = bh[nf >> 1][(nf & 1) * 2 + 1];
          uint32_t b0l = bl[nf >> 1][(nf & 1) * 2];
          uint32_t b1l = bl[nf >> 1][(nf & 1) * 2 + 1];
          MMA16816(c, ah[mf], b0h, b1h);  // Rh * Wh
          MMA16816(c, as[mf], b0l, b1l);  // (Rh*2^-6) * (Wl*2^6) = Rh * Wl
        }
    }
  };

  // --- mainloop: 2-stage ring; compute-then-load order (2-stage safe) ---
  load_chunk(0, 0);
  load_chunk(1, 1);
  for (int kc = 0; kc < KCHUNKS; ++kc) {
    const int s = kc & 1;
    const uint32_t j = (uint32_t)(kc >> 1);
    mbar_wait_parity(hdr + s * 8, j & 1);      // full[s] for chunk kc
    if (nfc == 6) computeT(IC<6>{}, s);
    else          computeT(IC<5>{}, s);
    if (kc + 2 < KCHUNKS) {
      mbar_wait_parity(hdr + 64 + s * 8, j & 1);  // all warps done reading s
      load_chunk(s, kc + 2);
    }
  }

  // --- fused epilogue: lam from indices; U = lam*(C+b) + (1-lam)*x_t; tanh ---
#pragma unroll
  for (int mf = 0; mf < 4; ++mf)
#pragma unroll
    for (int nf = 0; nf < 6; ++nf) {
      if (nf >= nfc) break;
#pragma unroll
      for (int half = 0; half < 2; ++half) {
        int m = m0 + wm + mf * 16 + (lane >> 2) + half * 8;
        int n = n0 + wn + nf * 8 + 2 * (lane & 3);
        size_t idx = (size_t)m * F_SIZE + n;
        float c0 = acc[mf][nf][half * 2 + 0] + b[n];
        float c1 = acc[mf][nf][half * 2 + 1] + b[n + 1];
        bool vis = (n < V_SIZE);
        float l0 = (vis && n != m) ? REC_F : 1.0f;
        float l1 = (vis && (n + 1) != m) ? REC_F : 1.0f;
        float u0 = l0 * c0;
        float u1 = l1 * c1;
        if (vis) {
          u0 = fmaf(1.f - l0, Xr[n], u0);
          u1 = fmaf(1.f - l1, Xr[n + 1], u1);
        }
        __half2 hv;
        hv.x = __float2half(fast_tanh(u0));
        hv.y = __float2half(fast_tanh(u1));
        *reinterpret_cast<__half2*>(O + idx) = hv;
      }
    }
}

// -------- final step (t=63): output needs only diag(U[:, :V]) --------
// lam[i,i] = 1  =>  diag[i] = dot(R_63[i,:], W[i,:]) + b[i]   (fp32 W, exact)
__global__ void __launch_bounds__(256, 1)
diag_kernel(const float* __restrict__ W, const float* __restrict__ b,
            float* __restrict__ diag) {
  const int lane = threadIdx.x & 31;
  const int row = blockIdx.x * 8 + (threadIdx.x >> 5);
  if (row >= V_SIZE) return;

  const __half* __restrict__ r = g_R[1] + (size_t)row * F_SIZE;
  const float* __restrict__ w = W + (size_t)row * F_SIZE;

  float acc = 0.f;
#pragma unroll
  for (int k0 = lane * 4; k0 < F_SIZE; k0 += 128) {
    __half2 rv01 = *reinterpret_cast<const __half2*>(r + k0);
    __half2 rv23 = *reinterpret_cast<const __half2*>(r + k0 + 2);
    float4 wv = *reinterpret_cast<const float4*>(w + k0);
    float2 f01 = __half22float2(rv01);
    float2 f23 = __half22float2(rv23);
    acc = fmaf(f01.x, wv.x, acc);
    acc = fmaf(f01.y, wv.y, acc);
    acc = fmaf(f23.x, wv.z, acc);
    acc = fmaf(f23.y, wv.w, acc);
  }
#pragma unroll
  for (int off = 16; off > 0; off >>= 1)
    acc += __shfl_xor_sync(0xFFFFFFFFu, acc, off);
  if (lane == 0) diag[row] = acc + b[row];
}

// ---------------- host launch ----------------
extern "C" void kernel_launch(void* const* d_in, const int* in_sizes, int n_in,
                              void* d_out, int out_size) {
  const float* X = (const float*)d_in[0];    // [T, V]
  const float* W = (const float*)d_in[1];    // [F, F]
  const float* b = (const float*)d_in[2];    // [F]
  const float* lam = (const float*)d_in[3];  // [V, F]
  float* out = (float*)d_out;                // [V]

  // SM-count-parametric tiling: tiles/band = P/4; 88-wide count per band
  // nW = 384 - 10*(P/4)  (P=152 -> 4x88+34x80; P=148 -> 14x88+23x80).
  int P = 148;
  cudaDeviceGetAttribute(&P, cudaDevAttrMultiProcessorCount, 0);
  int tpb = P / 4;
  int nW = 384 - 10 * tpb;
  int nN = tpb - nW;
  if (nW < 0 || nN < 0) { nW = 14; nN = 23; P = 148; }  // safety fallback

  cudaFuncSetAttribute(gemm_step_kernel,
                       cudaFuncAttributeMaxDynamicSharedMemorySize, SMEM_BYTES);

  split_w_kernel<<<2048, 512>>>(W);
  step0_kernel<<<2048, 512>>>(X, b, lam);

  dim3 grid(2 * P);  // one exact double wave: 2 CTAs per SM
  for (int t = 1; t < T_STEPS - 1; ++t) {  // t = 1..62
    gemm_step_kernel<<<grid, NTHREADS, SMEM_BYTES>>>(t, X, b, nW, nN);
  }
  diag_kernel<<<V_SIZE / 8, 256>>>(W, b, out);  // t = 63, diag only
}

// round 14
// speedup vs baseline: 1.0961x; 1.0961x over previous
#include <cuda_runtime.h>
#include <cuda_fp16.h>
#include <cstdint>
#include <cstddef>

// ---------------- problem constants ----------------
#define V_SIZE 1024
#define H_SIZE 2048
#define F_SIZE 3072
#define T_STEPS 64
#define REC_F 0.8f

// ---------------- GEMM tiling (mixed-width, dual-CTA-per-SM) ----------------
#define BM 128
#define BK 64
#define KCHUNKS (F_SIZE / BK)   // 48
#define NTHREADS 128            // 4 warps: 2(M) x 2(N)
#define NSTAGES 2

#define OFF_A  0
#define OFF_BH 16384
#define STAGE_BYTES 38912       // A(16K) + 2 x B(<=11264)
#define SMEM_BYTES (1024 + 1024 + NSTAGES * STAGE_BYTES)

// ---------------- device scratch ----------------
__device__ __half g_Wh[(size_t)F_SIZE * F_SIZE];
__device__ __half g_Wl[(size_t)F_SIZE * F_SIZE];
__device__ __half g_R[2][(size_t)V_SIZE * F_SIZE];

__device__ __forceinline__ uint32_t swz(uint32_t o) { return o ^ ((o >> 3) & 0x70u); }

#define LDM4(R_, A_)                                                              \
  asm volatile("ldmatrix.sync.aligned.m8n8.x4.shared.b16 {%0,%1,%2,%3}, [%4];"    \
               : "=r"((R_)[0]), "=r"((R_)[1]), "=r"((R_)[2]), "=r"((R_)[3])       \
               : "r"(A_))

#define LDM2(R_, A_)                                                              \
  asm volatile("ldmatrix.sync.aligned.m8n8.x2.shared.b16 {%0,%1}, [%2];"          \
               : "=r"((R_)[0]), "=r"((R_)[1]) : "r"(A_))

#define MMA16816(C_, A_, B0_, B1_)                                                \
  asm volatile("mma.sync.aligned.m16n8k16.row.col.f32.f16.f16.f32 "               \
               "{%0,%1,%2,%3},{%4,%5,%6,%7},{%8,%9},{%0,%1,%2,%3};"               \
               : "+f"((C_)[0]), "+f"((C_)[1]), "+f"((C_)[2]), "+f"((C_)[3])       \
               : "r"((A_)[0]), "r"((A_)[1]), "r"((A_)[2]), "r"((A_)[3]),          \
                 "r"(B0_), "r"(B1_))

#define CP16(SO_, G_)                                                             \
  asm volatile("cp.async.cg.shared.global [%0], [%1], 16;" :: "r"(SO_), "l"(G_))

#define CP_ASYNC_MBAR_ARRIVE_NOINC(mbar)                                          \
  asm volatile("cp.async.mbarrier.arrive.noinc.shared.b64 [%0];"                  \
               :: "r"((uint32_t)(mbar)) : "memory")

#define MBARRIER_INIT(mbar, count)                                                \
  asm volatile("mbarrier.init.shared.b64 [%0], %1;"                               \
               :: "r"((uint32_t)(mbar)), "r"((uint32_t)(count)) : "memory")
#define MBARRIER_ARRIVE(mbar)                                                     \
  asm volatile("mbarrier.arrive.shared.b64 _, [%0];"                              \
               :: "r"((uint32_t)(mbar)) : "memory")

__device__ __forceinline__ void mbar_wait_parity(uint32_t mbar, uint32_t parity) {
  uint32_t done;
  asm volatile("{\n\t.reg .pred p;\n\t"
               "mbarrier.try_wait.parity.acquire.cta.shared::cta.b64 p, [%1], %2;\n\t"
               "selp.b32 %0, 1, 0, p;\n\t}"
               : "=r"(done) : "r"(mbar), "r"(parity) : "memory");
  if (!done) {
    asm volatile("{\n\t.reg .pred P1;\n\t"
                 "WAIT_LOOP_%=:\n\t"
                 "mbarrier.try_wait.parity.acquire.cta.shared::cta.b64 P1, [%0], %1, 0x989680;\n\t"
                 "@P1 bra.uni WAIT_DONE_%=;\n\t"
                 "bra.uni WAIT_LOOP_%=;\n\t"
                 "WAIT_DONE_%=:\n\t}"
                 :: "r"(mbar), "r"(parity) : "memory");
  }
}

#define HALF2_POW2_M6 0x24002400u
__device__ __forceinline__ uint32_t hmul2_scale(uint32_t a) {
  uint32_t r;
  asm volatile("mul.f16x2 %0, %1, %2;" : "=r"(r) : "r"(a), "r"(HALF2_POW2_M6));
  return r;
}

__device__ __forceinline__ float fast_tanh(float x) {
  float e = __expf(2.f * x);
  return 1.f - __fdividef(2.f, e + 1.f);
}

// -------- W split: fp32 -> fp16 hi + fp16 lo (lo pre-scaled by 2^6) --------
__global__ void split_w_kernel(const float* __restrict__ W) {
  const int n = F_SIZE * F_SIZE;
  for (int i = blockIdx.x * blockDim.x + threadIdx.x; i < n;
       i += gridDim.x * blockDim.x) {
    float w = W[i];
    __half h = __float2half(w);
    g_Wh[i] = h;
    g_Wl[i] = __float2half((w - __half2float(h)) * 64.f);
  }
}

// -------- step 0: R_0 = 0, epilogue-only --------
__global__ void step0_kernel(const float* __restrict__ X,
                             const float* __restrict__ b,
                             const float* __restrict__ lam) {
  const int n = V_SIZE * F_SIZE;
  for (int i = blockIdx.x * blockDim.x + threadIdx.x; i < n;
       i += gridDim.x * blockDim.x) {
    int c = i % F_SIZE;
    float l = lam[i];
    float u = l * b[c];
    if (c < V_SIZE) u += (1.f - l) * X[c];  // x_0
    g_R[1][i] = __float2half(tanhf(u));
  }
}

// ===== fully compile-time tile body: WIDTH cols, this warp NF frags @ WN =====
template <int WIDTH, int NF, int WN>
__device__ __forceinline__ void tile_body(
    int m0, int n0, int t, const float* __restrict__ X,
    const float* __restrict__ b, uint32_t hdr, uint32_t tiles) {
  constexpr int BITEMS = WIDTH * 8;            // 16B chunks per B tile
  constexpr int TOT = 1024 + 2 * BITEMS;       // 2432 (88) / 2304 (80)
  constexpr int NITER = TOT / NTHREADS;        // 19 / 18, exact
  constexpr uint32_t OFF_BL = OFF_BH + (uint32_t)BITEMS * 16;

  const __half* __restrict__ A = g_R[t & 1];
  __half* __restrict__ O = g_R[(t + 1) & 1];
  const float* __restrict__ Xr = X + (size_t)t * V_SIZE;

  const int tid = threadIdx.x;
  const int lane = tid & 31;
  const int wid = tid >> 5;
  const int wm = (wid >> 1) * 64;              // 0 / 64

  const __half* __restrict__ srcA  = A + (size_t)m0 * F_SIZE;
  const __half* __restrict__ srcBh = g_Wh + (size_t)n0 * F_SIZE;
  const __half* __restrict__ srcBl = g_Wl + (size_t)n0 * F_SIZE;

  float acc[4][NF][4];
#pragma unroll
  for (int i = 0; i < 4; ++i)
#pragma unroll
    for (int j = 0; j < NF; ++j)
#pragma unroll
      for (int k = 0; k < 4; ++k) acc[i][j][k] = 0.f;

  // --- fully-unrolled constant-bound loader ---
  auto load_chunk = [&](int stage, int kc) {
    const uint32_t sb = tiles + (uint32_t)stage * STAGE_BYTES;
    const int koff = kc * BK;
#pragma unroll
    for (int it = 0; it < NITER; ++it) {
      int i = tid + it * NTHREADS;
      const __half* gb;
      uint32_t stile;
      int j;
      if (i < 1024)            { j = i;                 gb = srcA;  stile = OFF_A;  }
      else if (i < 1024 + BITEMS) { j = i - 1024;       gb = srcBh; stile = OFF_BH; }
      else                     { j = i - 1024 - BITEMS; gb = srcBl; stile = OFF_BL; }
      int r = j >> 3, c = j & 7;
      const void* g = gb + (size_t)r * F_SIZE + koff + c * 8;
      uint32_t so = sb + stile + swz((uint32_t)(r * 128 + c * 16));
      CP16(so, g);
    }
    CP_ASYNC_MBAR_ARRIVE_NOINC(hdr + stage * 8);  // full[stage]
  };

  // --- compute one staged chunk; empty-arrive after last LDSM ---
  auto compute = [&](int stage) {
    const uint32_t sb = tiles + (uint32_t)stage * STAGE_BYTES;
    const uint32_t aT = sb + OFF_A;
    const uint32_t bH = sb + OFF_BH;
    const uint32_t bL = sb + OFF_BL;
#pragma unroll
    for (int ks = 0; ks < 4; ++ks) {
      uint32_t ah[4][4], as[4][4], bh[(NF + 1) / 2][4], bl[(NF + 1) / 2][4];
#pragma unroll
      for (int mf = 0; mf < 4; ++mf) {
        uint32_t off = swz((uint32_t)((wm + mf * 16 + (lane & 15)) * 128 +
                                      (ks * 16 + ((lane >> 4) << 3)) * 2));
        LDM4(ah[mf], aT + off);
#pragma unroll
        for (int q = 0; q < 4; ++q) as[mf][q] = hmul2_scale(ah[mf][q]);
      }
#pragma unroll
      for (int nf2 = 0; nf2 < NF / 2; ++nf2) {
        uint32_t off = swz((uint32_t)(
            (WN + nf2 * 16 + (lane & 7) + (((lane >> 4) & 1) << 3)) * 128 +
            (ks * 16 + ((lane >> 3) & 1) * 8) * 2));
        LDM4(bh[nf2], bH + off);
        LDM4(bl[nf2], bL + off);
      }
      if (NF & 1) {  // trailing 8-col fragment via x2
        uint32_t off = swz((uint32_t)(
            (WN + (NF / 2) * 16 + (lane & 7)) * 128 +
            (ks * 16 + ((lane >> 3) & 1) * 8) * 2));
        LDM2(bh[NF / 2], bH + off);
        LDM2(bl[NF / 2], bL + off);
      }
      if (ks == 3) MBARRIER_ARRIVE(hdr + 64 + stage * 8);  // empty[stage]
#pragma unroll
      for (int mf = 0; mf < 4; ++mf)
#pragma unroll
        for (int nf = 0; nf < NF; ++nf) {
          float* c = acc[mf][nf];
          uint32_t b0h = bh[nf >> 1][(nf & 1) * 2];
          uint32_t b1h = bh[nf >> 1][(nf & 1) * 2 + 1];
          uint32_t b0l = bl[nf >> 1][(nf & 1) * 2];
          uint32_t b1l = bl[nf >> 1][(nf & 1) * 2 + 1];
          MMA16816(c, ah[mf], b0h, b1h);  // Rh * Wh
          MMA16816(c, as[mf], b0l, b1l);  // (Rh*2^-6) * (Wl*2^6) = Rh * Wl
        }
    }
  };

  // --- mainloop: 2-stage ring; compute-then-load order (2-stage safe) ---
  load_chunk(0, 0);
  load_chunk(1, 1);
  for (int kc = 0; kc < KCHUNKS; ++kc) {
    const int s = kc & 1;
    const uint32_t j = (uint32_t)(kc >> 1);
    mbar_wait_parity(hdr + s * 8, j & 1);      // full[s] for chunk kc
    compute(s);                                 // empty-arrive inside (ks==3)
    if (kc + 2 < KCHUNKS) {
      mbar_wait_parity(hdr + 64 + s * 8, j & 1);  // all warps done reading s
      load_chunk(s, kc + 2);
    }
  }

  // --- fused epilogue: lam from indices; U = lam*(C+b) + (1-lam)*x_t; tanh ---
#pragma unroll
  for (int mf = 0; mf < 4; ++mf)
#pragma unroll
    for (int nf = 0; nf < NF; ++nf)
#pragma unroll
      for (int half = 0; half < 2; ++half) {
        int m = m0 + wm + mf * 16 + (lane >> 2) + half * 8;
        int n = n0 + WN + nf * 8 + 2 * (lane & 3);
        size_t idx = (size_t)m * F_SIZE + n;
        float c0 = acc[mf][nf][half * 2 + 0] + b[n];
        float c1 = acc[mf][nf][half * 2 + 1] + b[n + 1];
        bool vis = (n < V_SIZE);  // n even -> pair stays inside block
        float l0 = (vis && n != m) ? REC_F : 1.0f;
        float l1 = (vis && (n + 1) != m) ? REC_F : 1.0f;
        float u0 = l0 * c0;
        float u1 = l1 * c1;
        if (vis) {
          u0 = fmaf(1.f - l0, Xr[n], u0);
          u1 = fmaf(1.f - l1, Xr[n + 1], u1);
        }
        __half2 hv;
        hv.x = __float2half(fast_tanh(u0));
        hv.y = __float2half(fast_tanh(u1));
        *reinterpret_cast<__half2*>(O + idx) = hv;
      }
}

// -------- steps 1..62: mixed-width tiles (wide 88 first, then narrow 80) ----
__global__ void __launch_bounds__(NTHREADS, 2)
gemm_step_kernel(int t, const float* __restrict__ X, const float* __restrict__ b,
                 int nW, int nN) {
  extern __shared__ unsigned char smem_raw[];
  uint32_t sbase = (uint32_t)__cvta_generic_to_shared(smem_raw);
  sbase = (sbase + 1023u) & ~1023u;
  const uint32_t hdr = sbase;        // full[s]=hdr+s*8, empty[s]=hdr+64+s*8
  const uint32_t tiles = sbase + 1024;

  if (threadIdx.x == 0) {
#pragma unroll
    for (int s = 0; s < NSTAGES; ++s) {
      MBARRIER_INIT(hdr + s * 8, NTHREADS);       // full[s]
      MBARRIER_INIT(hdr + 64 + s * 8, NTHREADS);  // empty[s]
    }
  }
  __syncthreads();

  // once-per-CTA mapping (runtime divide is negligible here)
  const int bid = blockIdx.x;
  const int wid = threadIdx.x >> 5;
  const int wideTotal = nW * 8;
  if (bid < wideTotal) {
    int band = bid / nW;
    int n0 = (bid % nW) * 88;
    if ((wid & 1) == 0) tile_body<88, 6, 0>(band * BM, n0, t, X, b, hdr, tiles);
    else                tile_body<88, 5, 48>(band * BM, n0, t, X, b, hdr, tiles);
  } else {
    int idx = bid - wideTotal;
    int band = idx / nN;
    int n0 = nW * 88 + (idx % nN) * 80;
    if ((wid & 1) == 0) tile_body<80, 5, 0>(band * BM, n0, t, X, b, hdr, tiles);
    else                tile_body<80, 5, 40>(band * BM, n0, t, X, b, hdr, tiles);
  }
}

// -------- final step (t=63): output needs only diag(U[:, :V]) --------
// lam[i,i] = 1  =>  diag[i] = dot(R_63[i,:], W[i,:]) + b[i]   (fp32 W, exact)
__global__ void __launch_bounds__(256, 1)
diag_kernel(const float* __restrict__ W, const float* __restrict__ b,
            float* __restrict__ diag) {
  const int lane = threadIdx.x & 31;
  const int row = blockIdx.x * 8 + (threadIdx.x >> 5);
  if (row >= V_SIZE) return;

  const __half* __restrict__ r = g_R[1] + (size_t)row * F_SIZE;
  const float* __restrict__ w = W + (size_t)row * F_SIZE;

  float acc = 0.f;
#pragma unroll
  for (int k0 = lane * 4; k0 < F_SIZE; k0 += 128) {
    __half2 rv01 = *reinterpret_cast<const __half2*>(r + k0);
    __half2 rv23 = *reinterpret_cast<const __half2*>(r + k0 + 2);
    float4 wv = *reinterpret_cast<const float4*>(w + k0);
    float2 f01 = __half22float2(rv01);
    float2 f23 = __half22float2(rv23);
    acc = fmaf(f01.x, wv.x, acc);
    acc = fmaf(f01.y, wv.y, acc);
    acc = fmaf(f23.x, wv.z, acc);
    acc = fmaf(f23.y, wv.w, acc);
  }
#pragma unroll
  for (int off = 16; off > 0; off >>= 1)
    acc += __shfl_xor_sync(0xFFFFFFFFu, acc, off);
  if (lane == 0) diag[row] = acc + b[row];
}

// ---------------- host launch ----------------
extern "C" void kernel_launch(void* const* d_in, const int* in_sizes, int n_in,
                              void* d_out, int out_size) {
  const float* X = (const float*)d_in[0];    // [T, V]
  const float* W = (const float*)d_in[1];    // [F, F]
  const float* b = (const float*)d_in[2];    // [F]
  const float* lam = (const float*)d_in[3];  // [V, F]
  float* out = (float*)d_out;                // [V]

  // Per-band tile mix: nW*88 + nN*80 = 3072, tiles/band matched to P/4.
  int P = 152;
  cudaDeviceGetAttribute(&P, cudaDevAttrMultiProcessorCount, 0);
  int nW = 4, nN = 34;                       // P = 152 default
  if (P % 4 == 0) {
    int tpb = P / 4;
    int w = 384 - 10 * tpb;
    if (w >= 0 && (tpb - w) >= 0) { nW = w; nN = tpb - w; }
  }

  cudaFuncSetAttribute(gemm_step_kernel,
                       cudaFuncAttributeMaxDynamicSharedMemorySize, SMEM_BYTES);

  split_w_kernel<<<2048, 512>>>(W);
  step0_kernel<<<2048, 512>>>(X, b, lam);

  dim3 grid(8 * (nW + nN));                  // 304 @ P=152: exact double wave
  for (int t = 1; t < T_STEPS - 1; ++t) {    // t = 1..62
    gemm_step_kernel<<<grid, NTHREADS, SMEM_BYTES>>>(t, X, b, nW, nN);
  }
  diag_kernel<<<V_SIZE / 8, 256>>>(W, b, out);  // t = 63, diag only
}